// round 8
// baseline (speedup 1.0000x reference)
#include <cuda_runtime.h>
#include <cstdint>

// Problem constants
#define B_ROWS    1024
#define IN_FEAT   76800
#define IN_G      19200     // IN_FEAT/4 (float4 / int8x4 groups)
#define OUT_FEAT  10
#define W_ELEMS   (OUT_FEAT * IN_FEAT)   // 768000
#define W_G       (OUT_FEAT * IN_G)      // 192000 packed groups

// chunked pipeline
#define NCHUNK    4
#define CH_ROWS   (B_ROWS / NCHUNK)      // 256

// rowmax kernel
#define QT        768
#define QK        25                     // 25*768 = 19200

// gemv kernel: 10 slices x 29 rowblocks, 384 thr (proven round-7 shape)
#define NSLICE    10
#define SLICE_G   (IN_G / NSLICE)        // 1920 groups
#define GT        384
#define GPT       (SLICE_G / GT)         // 5 k-steps/thread
#define ROWBLK    29
#define SWQ_WORDS (OUT_FEAT * GT * 4)
#define GEMV_SMEM ((SWQ_WORDS + OUT_FEAT * GT) * 4)   // 76800 B

// wsum reduction
#define WSUM_BLOCKS 125
#define WSUM_THREADS 256

// ---------------- device scratch (static, allocation-free) ----------------
__device__ float    g_wpart[WSUM_BLOCKS];
__device__ float    g_wscale;               // 1/clip(mean|W|,eps)
__device__ float    g_winv;                 // clip(mean|W|,eps)
__device__ float    g_rowscale[B_ROWS];     // 127/clip(rowmax,eps)
__device__ unsigned g_tw[W_G];              // ternary weights, packed int8x4, [o][g]
__device__ int      g_dot[B_ROWS * OUT_FEAT];

// ---------------- kernel 1: sum |W| ----------------
__global__ void k_wsum(const float4* __restrict__ w4) {
    float s = 0.f;
    int idx = blockIdx.x * WSUM_THREADS + threadIdx.x;
    #pragma unroll
    for (int k = 0; k < 6; k++) {   // 125*256*6 = 192000 exactly
        float4 v = w4[idx + k * WSUM_BLOCKS * WSUM_THREADS];
        s += fabsf(v.x) + fabsf(v.y) + fabsf(v.z) + fabsf(v.w);
    }
    #pragma unroll
    for (int d = 16; d; d >>= 1) s += __shfl_down_sync(0xffffffffu, s, d);
    __shared__ float red[8];
    int warp = threadIdx.x >> 5, lane = threadIdx.x & 31;
    if (lane == 0) red[warp] = s;
    __syncthreads();
    if (threadIdx.x < 8) {
        float v = red[threadIdx.x];
        #pragma unroll
        for (int d = 4; d; d >>= 1) v += __shfl_down_sync(0xffu, v, d);
        if (threadIdx.x == 0) g_wpart[blockIdx.x] = v;
    }
}

// ---------------- kernel 2: finalize wscale ----------------
__global__ void k_wscale(void) {
    float s = (threadIdx.x < WSUM_BLOCKS) ? g_wpart[threadIdx.x] : 0.f;
    #pragma unroll
    for (int d = 16; d; d >>= 1) s += __shfl_down_sync(0xffffffffu, s, d);
    __shared__ float red[4];
    int warp = threadIdx.x >> 5, lane = threadIdx.x & 31;
    if (lane == 0) red[warp] = s;
    __syncthreads();
    if (threadIdx.x == 0) {
        float total = red[0] + red[1] + red[2] + red[3];
        float mean = fmaxf(total / (float)W_ELEMS, 1e-5f);
        g_winv = mean;
        g_wscale = 1.f / mean;
    }
}

// ---------------- kernel 3: ternarize W into packed int8x4 ----------------
__global__ void k_ternary(const float4* __restrict__ w4) {
    int i = blockIdx.x * 256 + threadIdx.x;   // grid 750*256 = 192000
    float ws = g_wscale;
    float4 v = w4[i];
    int t0 = (int)fminf(1.f, fmaxf(-1.f, rintf(v.x * ws)));
    int t1 = (int)fminf(1.f, fmaxf(-1.f, rintf(v.y * ws)));
    int t2 = (int)fminf(1.f, fmaxf(-1.f, rintf(v.z * ws)));
    int t3 = (int)fminf(1.f, fmaxf(-1.f, rintf(v.w * ws)));
    g_tw[i] = (unsigned)((t0 & 0xFF) | ((t1 & 0xFF) << 8) | ((t2 & 0xFF) << 16) | (t3 << 24));
}

// ---------------- kernel 4: per-chunk row absmax (at DRAM roofline) ----------------
// Also zeroes g_dot for this row.
__global__ void __launch_bounds__(QT) k_rowmax(const float4* __restrict__ x4, int base) {
    const int row = base + blockIdx.x;
    const int tid = threadIdx.x;
    if (tid < OUT_FEAT) g_dot[row * OUT_FEAT + tid] = 0;

    const float4* xr = x4 + (size_t)row * IN_G;
    float m = 0.f;
    #pragma unroll 5
    for (int k = 0; k < QK; k++) {
        float4 v = xr[tid + k * QT];
        m = fmaxf(m, fmaxf(fmaxf(fabsf(v.x), fabsf(v.y)),
                           fmaxf(fabsf(v.z), fabsf(v.w))));
    }
    #pragma unroll
    for (int d = 16; d; d >>= 1) m = fmaxf(m, __shfl_down_sync(0xffffffffu, m, d));
    __shared__ float red[QT / 32];
    int warp = tid >> 5, lane = tid & 31;
    if (lane == 0) red[warp] = m;
    __syncthreads();
    if (tid < 32) {
        float v = (tid < QT / 32) ? red[tid] : 0.f;
        #pragma unroll
        for (int d = 16; d; d >>= 1) v = fmaxf(v, __shfl_down_sync(0xffffffffu, v, d));
        if (tid == 0) g_rowscale[row] = 127.f / fmaxf(v, 1e-5f);
    }
}

// FMA magic-number quantize: round-to-nearest-even of x*as in one FFMA.
// (validated: rel_err 5.6e-5, well under 1e-3)
__device__ __forceinline__ unsigned quant_pack(float4 v, float as) {
    float f0 = __fmaf_rn(v.x, as, 12582912.f);   // 1.5*2^23
    float f1 = __fmaf_rn(v.y, as, 12582912.f);
    float f2 = __fmaf_rn(v.z, as, 12582912.f);
    float f3 = __fmaf_rn(v.w, as, 12582912.f);
    unsigned p01 = __byte_perm(__float_as_uint(f0), __float_as_uint(f1), 0x0040);
    unsigned p23 = __byte_perm(__float_as_uint(f2), __float_as_uint(f3), 0x0040);
    return __byte_perm(p01, p23, 0x5410);
}

// ---------------- kernel 5: fused quantize + ternary GEMV, row-PAIR batched ----------------
// Per-chunk launch over rows [base, base+CH_ROWS). Internals identical to the
// proven round-7 kernel: 2 rows per iter, 10 LDG.128 up-front, each weight LDS
// serves both rows, REDUX + exact integer atomics, no syncs in the loop.
__global__ void __launch_bounds__(GT, 2) k_gemv(const float4* __restrict__ x4, int base) {
    extern __shared__ unsigned smem[];
    uint4*    swq = (uint4*)smem;                 // [10][GT] quads (k=0..3)
    unsigned* sws = smem + SWQ_WORDS;             // [10][GT] singles (k=4)

    const int s = blockIdx.x;
    const int rb = blockIdx.y;
    const int tid = threadIdx.x;
    const int lane = tid & 31;
    const int gbase = s * SLICE_G;

    // one-time weight staging (L2-resident source)
    #pragma unroll
    for (int o = 0; o < OUT_FEAT; o++) {
        uint4 w;
        w.x = g_tw[o * IN_G + gbase + 0 * GT + tid];
        w.y = g_tw[o * IN_G + gbase + 1 * GT + tid];
        w.z = g_tw[o * IN_G + gbase + 2 * GT + tid];
        w.w = g_tw[o * IN_G + gbase + 3 * GT + tid];
        swq[o * GT + tid] = w;
        sws[o * GT + tid] = g_tw[o * IN_G + gbase + 4 * GT + tid];
    }
    __syncthreads();

    const float4* xb = x4 + gbase + tid;   // thread-fixed base

    int r0 = base + CH_ROWS - 1 - rb;      // descending within chunk (L2 tail)
    while (r0 >= base) {
        const int r1 = r0 - ROWBLK;
        const int r1c = (r1 >= base) ? r1 : r0;   // tail: duplicate row, skip 2nd atomic

        // issue all 10 LDGs up-front (5KB in flight per thread)
        float4 v0[GPT], v1[GPT];
        #pragma unroll
        for (int k = 0; k < GPT; k++) v0[k] = xb[(size_t)r0 * IN_G + k * GT];
        #pragma unroll
        for (int k = 0; k < GPT; k++) v1[k] = xb[(size_t)r1c * IN_G + k * GT];
        const float as0 = g_rowscale[r0];
        const float as1 = g_rowscale[r1c];

        unsigned q0[GPT], q1[GPT];
        #pragma unroll
        for (int k = 0; k < GPT; k++) { q0[k] = quant_pack(v0[k], as0);
                                        q1[k] = quant_pack(v1[k], as1); }

        // each weight load feeds BOTH rows
        int acc0[OUT_FEAT], acc1[OUT_FEAT];
        #pragma unroll
        for (int o = 0; o < OUT_FEAT; o++) {
            const uint4 w = swq[o * GT + tid];
            const int ws4 = (int)sws[o * GT + tid];
            int a0 = __dp4a((int)q0[0], (int)w.x, 0);
            int a1 = __dp4a((int)q1[0], (int)w.x, 0);
            a0 = __dp4a((int)q0[1], (int)w.y, a0);
            a1 = __dp4a((int)q1[1], (int)w.y, a1);
            a0 = __dp4a((int)q0[2], (int)w.z, a0);
            a1 = __dp4a((int)q1[2], (int)w.z, a1);
            a0 = __dp4a((int)q0[3], (int)w.w, a0);
            a1 = __dp4a((int)q1[3], (int)w.w, a1);
            acc0[o] = __dp4a((int)q0[4], ws4, a0);
            acc1[o] = __dp4a((int)q1[4], ws4, a1);
        }

        #pragma unroll
        for (int o = 0; o < OUT_FEAT; o++) {
            acc0[o] = __reduce_add_sync(0xffffffffu, acc0[o]);
            acc1[o] = __reduce_add_sync(0xffffffffu, acc1[o]);
        }
        if (lane == 0) {
            int* d0 = g_dot + r0 * OUT_FEAT;
            #pragma unroll
            for (int o = 0; o < OUT_FEAT; o++) atomicAdd(d0 + o, acc0[o]);
            if (r1 >= base) {
                int* d1 = g_dot + r1 * OUT_FEAT;
                #pragma unroll
                for (int o = 0; o < OUT_FEAT; o++) atomicAdd(d1 + o, acc1[o]);
            }
        }
        r0 -= 2 * ROWBLK;
    }
}

// ---------------- kernel 6: scale, bias, softmax ----------------
__global__ void k_finish(const float* __restrict__ bias, float* __restrict__ out) {
    int row = blockIdx.x * 128 + threadIdx.x;   // grid 8 x 128
    float inv_as = 1.f / g_rowscale[row];
    float coef = inv_as * g_winv;
    const int* dp = g_dot + row * OUT_FEAT;
    float logit[OUT_FEAT];
    float m = -3.4e38f;
    #pragma unroll
    for (int o = 0; o < OUT_FEAT; o++) {
        logit[o] = coef * (float)dp[o] + bias[o];
        m = fmaxf(m, logit[o]);
    }
    float ssum = 0.f;
    #pragma unroll
    for (int o = 0; o < OUT_FEAT; o++) { logit[o] = expf(logit[o] - m); ssum += logit[o]; }
    float inv_s = 1.f / ssum;
    #pragma unroll
    for (int o = 0; o < OUT_FEAT; o++) out[row * OUT_FEAT + o] = logit[o] * inv_s;
}

// ---------------- launch: chunked rowmax/gemv overlap ----------------
// stream0: weights-fork, then rowmax chunk 0..3 (each records an event).
// side:    weight chain, then for each chunk: wait rowmax(c) -> gemv(c); finish.
// stream0 joins on the final event so the harness sees completion.
extern "C" void kernel_launch(void* const* d_in, const int* in_sizes, int n_in,
                              void* d_out, int out_size) {
    const float4* x4 = (const float4*)d_in[0];   // [1024,3,160,160] fp32
    const float4* w4 = (const float4*)d_in[1];   // [10,76800] fp32
    const float*  b  = (const float*)d_in[2];    // [10]
    float* out = (float*)d_out;

    static cudaStream_t s_side = nullptr;
    static cudaEvent_t ev_fork = nullptr, ev_done = nullptr;
    static cudaEvent_t ev_rm[NCHUNK];
    static int init_done = 0;
    if (!init_done) {
        cudaStreamCreateWithFlags(&s_side, cudaStreamNonBlocking);
        cudaEventCreateWithFlags(&ev_fork, cudaEventDisableTiming);
        cudaEventCreateWithFlags(&ev_done, cudaEventDisableTiming);
        for (int c = 0; c < NCHUNK; c++)
            cudaEventCreateWithFlags(&ev_rm[c], cudaEventDisableTiming);
        cudaFuncSetAttribute(k_gemv, cudaFuncAttributeMaxDynamicSharedMemorySize, GEMV_SMEM);
        init_done = 1;
    }

    // fork: weight-prep chain on side stream
    cudaEventRecord(ev_fork, 0);
    cudaStreamWaitEvent(s_side, ev_fork, 0);
    k_wsum<<<WSUM_BLOCKS, WSUM_THREADS, 0, s_side>>>(w4);
    k_wscale<<<1, 128, 0, s_side>>>();
    k_ternary<<<W_G / 256, 256, 0, s_side>>>(w4);

    // stream0: rowmax chunks (DRAM-saturating), one event per chunk
    for (int c = 0; c < NCHUNK; c++) {
        k_rowmax<<<CH_ROWS, QT>>>(x4, c * CH_ROWS);
        cudaEventRecord(ev_rm[c], 0);
    }

    // side: gemv chunk c as soon as rowmax chunk c is done (overlaps chunk c+1..)
    dim3 ggrid(NSLICE, ROWBLK);
    for (int c = 0; c < NCHUNK; c++) {
        cudaStreamWaitEvent(s_side, ev_rm[c], 0);
        k_gemv<<<ggrid, GT, GEMV_SMEM, s_side>>>(x4, c * CH_ROWS);
    }
    k_finish<<<B_ROWS / 128, 128, 0, s_side>>>(b, out);
    cudaEventRecord(ev_done, s_side);
    cudaStreamWaitEvent(0, ev_done, 0);   // join back to launch stream
}

// round 9
// speedup vs baseline: 1.3394x; 1.3394x over previous
#include <cuda_runtime.h>
#include <cstdint>

// Problem constants
#define B_ROWS    1024
#define IN_FEAT   76800
#define IN_G      19200     // IN_FEAT/4 (float4 / int8x4 groups)
#define OUT_FEAT  10
#define W_ELEMS   (OUT_FEAT * IN_FEAT)   // 768000
#define W_G       (OUT_FEAT * IN_G)      // 192000 packed groups

// rowmax kernel
#define QT        768
#define QK        25                     // 25*768 = 19200

// gemv kernel: 10 slices x 29 rowblocks = 290 CTAs (one wave at 2/SM), 384 thr
#define NSLICE    10
#define SLICE_G   (IN_G / NSLICE)        // 1920 groups
#define GT        384
#define GPT       (SLICE_G / GT)         // 5 k-steps/thread
#define ROWBLK    29
#define SWQ_WORDS (OUT_FEAT * GT * 4)
#define GEMV_SMEM ((SWQ_WORDS + OUT_FEAT * GT) * 4)   // 76800 B

// wsum reduction
#define WSUM_BLOCKS 125
#define WSUM_THREADS 256

// ---------------- device scratch (static, allocation-free) ----------------
__device__ float    g_wpart[WSUM_BLOCKS];
__device__ float    g_wscale;               // 1/clip(mean|W|,eps)
__device__ float    g_winv;                 // clip(mean|W|,eps)
__device__ float    g_rowscale[B_ROWS];     // 127/clip(rowmax,eps)
__device__ unsigned g_tw[W_G];              // ternary weights, packed int8x4, [o][g]
__device__ int      g_dot[B_ROWS * OUT_FEAT];

// ---------------- kernel 1: sum |W| ----------------
__global__ void k_wsum(const float4* __restrict__ w4) {
    float s = 0.f;
    int idx = blockIdx.x * WSUM_THREADS + threadIdx.x;
    #pragma unroll
    for (int k = 0; k < 6; k++) {   // 125*256*6 = 192000 exactly
        float4 v = w4[idx + k * WSUM_BLOCKS * WSUM_THREADS];
        s += fabsf(v.x) + fabsf(v.y) + fabsf(v.z) + fabsf(v.w);
    }
    #pragma unroll
    for (int d = 16; d; d >>= 1) s += __shfl_down_sync(0xffffffffu, s, d);
    __shared__ float red[8];
    int warp = threadIdx.x >> 5, lane = threadIdx.x & 31;
    if (lane == 0) red[warp] = s;
    __syncthreads();
    if (threadIdx.x < 8) {
        float v = red[threadIdx.x];
        #pragma unroll
        for (int d = 4; d; d >>= 1) v += __shfl_down_sync(0xffu, v, d);
        if (threadIdx.x == 0) g_wpart[blockIdx.x] = v;
    }
}

// ---------------- kernel 2: finalize wscale ----------------
__global__ void k_wscale(void) {
    float s = (threadIdx.x < WSUM_BLOCKS) ? g_wpart[threadIdx.x] : 0.f;
    #pragma unroll
    for (int d = 16; d; d >>= 1) s += __shfl_down_sync(0xffffffffu, s, d);
    __shared__ float red[4];
    int warp = threadIdx.x >> 5, lane = threadIdx.x & 31;
    if (lane == 0) red[warp] = s;
    __syncthreads();
    if (threadIdx.x == 0) {
        float total = red[0] + red[1] + red[2] + red[3];
        float mean = fmaxf(total / (float)W_ELEMS, 1e-5f);
        g_winv = mean;
        g_wscale = 1.f / mean;
    }
}

// ---------------- kernel 3: ternarize W into packed int8x4 ----------------
__global__ void k_ternary(const float4* __restrict__ w4) {
    int i = blockIdx.x * 256 + threadIdx.x;   // grid 750*256 = 192000
    float ws = g_wscale;
    float4 v = w4[i];
    int t0 = (int)fminf(1.f, fmaxf(-1.f, rintf(v.x * ws)));
    int t1 = (int)fminf(1.f, fmaxf(-1.f, rintf(v.y * ws)));
    int t2 = (int)fminf(1.f, fmaxf(-1.f, rintf(v.z * ws)));
    int t3 = (int)fminf(1.f, fmaxf(-1.f, rintf(v.w * ws)));
    g_tw[i] = (unsigned)((t0 & 0xFF) | ((t1 & 0xFF) << 8) | ((t2 & 0xFF) << 16) | (t3 << 24));
}

// ---------------- kernel 4: per-row absmax (measured at DRAM roofline) ----------------
// Also zeroes g_dot for this row.
__global__ void __launch_bounds__(QT) k_rowmax(const float4* __restrict__ x4) {
    const int row = blockIdx.x;
    const int tid = threadIdx.x;
    if (tid < OUT_FEAT) g_dot[row * OUT_FEAT + tid] = 0;

    const float4* xr = x4 + (size_t)row * IN_G;
    float m = 0.f;
    #pragma unroll 5
    for (int k = 0; k < QK; k++) {
        float4 v = xr[tid + k * QT];
        m = fmaxf(m, fmaxf(fmaxf(fabsf(v.x), fabsf(v.y)),
                           fmaxf(fabsf(v.z), fabsf(v.w))));
    }
    #pragma unroll
    for (int d = 16; d; d >>= 1) m = fmaxf(m, __shfl_down_sync(0xffffffffu, m, d));
    __shared__ float red[QT / 32];
    int warp = tid >> 5, lane = tid & 31;
    if (lane == 0) red[warp] = m;
    __syncthreads();
    if (tid < 32) {
        float v = (tid < QT / 32) ? red[tid] : 0.f;
        #pragma unroll
        for (int d = 16; d; d >>= 1) v = fmaxf(v, __shfl_down_sync(0xffffffffu, v, d));
        if (tid == 0) g_rowscale[row] = 127.f / fmaxf(v, 1e-5f);
    }
}

// FMA magic-number quantize: round-to-nearest-even of x*as in one FFMA.
// (validated: rel_err 5.6e-5, well under 1e-3)
__device__ __forceinline__ unsigned quant_pack(float4 v, float as) {
    float f0 = __fmaf_rn(v.x, as, 12582912.f);   // 1.5*2^23
    float f1 = __fmaf_rn(v.y, as, 12582912.f);
    float f2 = __fmaf_rn(v.z, as, 12582912.f);
    float f3 = __fmaf_rn(v.w, as, 12582912.f);
    unsigned p01 = __byte_perm(__float_as_uint(f0), __float_as_uint(f1), 0x0040);
    unsigned p23 = __byte_perm(__float_as_uint(f2), __float_as_uint(f3), 0x0040);
    return __byte_perm(p01, p23, 0x5410);
}

// ---------------- kernel 5: fused quantize + ternary GEMV, row-TRIPLE batched ----------------
// 290 CTAs (2/SM, 24 warps/SM, 84-reg cap). Each iteration processes THREE
// rows: 15 LDG.128 issued up-front (7.5KB in flight/thread), each weight LDS
// serves all three rows. Transient reg peak ~78 (v dies at quant), compute
// phase ~60 — fits the cap without spills. No syncthreads in the loop.
__global__ void __launch_bounds__(GT, 2) k_gemv(const float4* __restrict__ x4) {
    extern __shared__ unsigned smem[];
    uint4*    swq = (uint4*)smem;                 // [10][GT] quads (k=0..3)
    unsigned* sws = smem + SWQ_WORDS;             // [10][GT] singles (k=4)

    const int s = blockIdx.x;
    const int rb = blockIdx.y;
    const int tid = threadIdx.x;
    const int lane = tid & 31;
    const int gbase = s * SLICE_G;

    // one-time weight staging (L2-resident source)
    #pragma unroll
    for (int o = 0; o < OUT_FEAT; o++) {
        uint4 w;
        w.x = g_tw[o * IN_G + gbase + 0 * GT + tid];
        w.y = g_tw[o * IN_G + gbase + 1 * GT + tid];
        w.z = g_tw[o * IN_G + gbase + 2 * GT + tid];
        w.w = g_tw[o * IN_G + gbase + 3 * GT + tid];
        swq[o * GT + tid] = w;
        sws[o * GT + tid] = g_tw[o * IN_G + gbase + 4 * GT + tid];
    }
    __syncthreads();

    const float4* xb = x4 + gbase + tid;   // thread-fixed base

    int r0 = B_ROWS - 1 - rb;              // descending (harvest rowmax L2 tail)
    while (r0 >= 0) {
        const int r1 = r0 - ROWBLK;
        const int r2 = r0 - 2 * ROWBLK;
        const int r1c = (r1 >= 0) ? r1 : r0;   // tail: dup row, skip its atomic
        const int r2c = (r2 >= 0) ? r2 : r0;

        // issue all 15 LDGs up-front (7.5KB in flight per thread)
        float4 v0[GPT], v1[GPT], v2[GPT];
        #pragma unroll
        for (int k = 0; k < GPT; k++) v0[k] = xb[(size_t)r0  * IN_G + k * GT];
        #pragma unroll
        for (int k = 0; k < GPT; k++) v1[k] = xb[(size_t)r1c * IN_G + k * GT];
        #pragma unroll
        for (int k = 0; k < GPT; k++) v2[k] = xb[(size_t)r2c * IN_G + k * GT];
        const float as0 = g_rowscale[r0];
        const float as1 = g_rowscale[r1c];
        const float as2 = g_rowscale[r2c];

        // quantize (v regs die here -> reg pressure drops for dp4a phase)
        unsigned q0[GPT], q1[GPT], q2[GPT];
        #pragma unroll
        for (int k = 0; k < GPT; k++) q0[k] = quant_pack(v0[k], as0);
        #pragma unroll
        for (int k = 0; k < GPT; k++) q1[k] = quant_pack(v1[k], as1);
        #pragma unroll
        for (int k = 0; k < GPT; k++) q2[k] = quant_pack(v2[k], as2);

        // each weight load feeds all THREE rows
        int acc0[OUT_FEAT], acc1[OUT_FEAT], acc2[OUT_FEAT];
        #pragma unroll
        for (int o = 0; o < OUT_FEAT; o++) {
            const uint4 w = swq[o * GT + tid];
            const int ws4 = (int)sws[o * GT + tid];
            int a0 = __dp4a((int)q0[0], (int)w.x, 0);
            int a1 = __dp4a((int)q1[0], (int)w.x, 0);
            int a2 = __dp4a((int)q2[0], (int)w.x, 0);
            a0 = __dp4a((int)q0[1], (int)w.y, a0);
            a1 = __dp4a((int)q1[1], (int)w.y, a1);
            a2 = __dp4a((int)q2[1], (int)w.y, a2);
            a0 = __dp4a((int)q0[2], (int)w.z, a0);
            a1 = __dp4a((int)q1[2], (int)w.z, a1);
            a2 = __dp4a((int)q2[2], (int)w.z, a2);
            a0 = __dp4a((int)q0[3], (int)w.w, a0);
            a1 = __dp4a((int)q1[3], (int)w.w, a1);
            a2 = __dp4a((int)q2[3], (int)w.w, a2);
            acc0[o] = __dp4a((int)q0[4], ws4, a0);
            acc1[o] = __dp4a((int)q1[4], ws4, a1);
            acc2[o] = __dp4a((int)q2[4], ws4, a2);
        }

        // warp reduce + exact integer atomics (order-independent)
        #pragma unroll
        for (int o = 0; o < OUT_FEAT; o++) {
            acc0[o] = __reduce_add_sync(0xffffffffu, acc0[o]);
            acc1[o] = __reduce_add_sync(0xffffffffu, acc1[o]);
            acc2[o] = __reduce_add_sync(0xffffffffu, acc2[o]);
        }
        if (lane == 0) {
            int* d0 = g_dot + r0 * OUT_FEAT;
            #pragma unroll
            for (int o = 0; o < OUT_FEAT; o++) atomicAdd(d0 + o, acc0[o]);
            if (r1 >= 0) {
                int* d1 = g_dot + r1 * OUT_FEAT;
                #pragma unroll
                for (int o = 0; o < OUT_FEAT; o++) atomicAdd(d1 + o, acc1[o]);
            }
            if (r2 >= 0) {
                int* d2 = g_dot + r2 * OUT_FEAT;
                #pragma unroll
                for (int o = 0; o < OUT_FEAT; o++) atomicAdd(d2 + o, acc2[o]);
            }
        }
        r0 -= 3 * ROWBLK;
    }
}

// ---------------- kernel 6: scale, bias, softmax ----------------
__global__ void k_finish(const float* __restrict__ bias, float* __restrict__ out) {
    int row = blockIdx.x * 128 + threadIdx.x;   // grid 8 x 128
    float inv_as = 1.f / g_rowscale[row];
    float coef = inv_as * g_winv;
    const int* dp = g_dot + row * OUT_FEAT;
    float logit[OUT_FEAT];
    float m = -3.4e38f;
    #pragma unroll
    for (int o = 0; o < OUT_FEAT; o++) {
        logit[o] = coef * (float)dp[o] + bias[o];
        m = fmaxf(m, logit[o]);
    }
    float ssum = 0.f;
    #pragma unroll
    for (int o = 0; o < OUT_FEAT; o++) { logit[o] = expf(logit[o] - m); ssum += logit[o]; }
    float inv_s = 1.f / ssum;
    #pragma unroll
    for (int o = 0; o < OUT_FEAT; o++) out[row * OUT_FEAT + o] = logit[o] * inv_s;
}

// ---------------- launch (fork/join: weight chain overlaps rowmax) ----------------
extern "C" void kernel_launch(void* const* d_in, const int* in_sizes, int n_in,
                              void* d_out, int out_size) {
    const float4* x4 = (const float4*)d_in[0];   // [1024,3,160,160] fp32
    const float4* w4 = (const float4*)d_in[1];   // [10,76800] fp32
    const float*  b  = (const float*)d_in[2];    // [10]
    float* out = (float*)d_out;

    static cudaStream_t s_side = nullptr;
    static cudaEvent_t ev_fork = nullptr, ev_join = nullptr;
    static int init_done = 0;
    if (!init_done) {
        cudaStreamCreateWithFlags(&s_side, cudaStreamNonBlocking);
        cudaEventCreateWithFlags(&ev_fork, cudaEventDisableTiming);
        cudaEventCreateWithFlags(&ev_join, cudaEventDisableTiming);
        cudaFuncSetAttribute(k_gemv, cudaFuncAttributeMaxDynamicSharedMemorySize, GEMV_SMEM);
        init_done = 1;
    }

    // fork: weight-prep chain on side stream, concurrent with k_rowmax
    cudaEventRecord(ev_fork, 0);
    cudaStreamWaitEvent(s_side, ev_fork, 0);
    k_wsum<<<WSUM_BLOCKS, WSUM_THREADS, 0, s_side>>>(w4);
    k_wscale<<<1, 128, 0, s_side>>>();
    k_ternary<<<W_G / 256, 256, 0, s_side>>>(w4);
    cudaEventRecord(ev_join, s_side);

    k_rowmax<<<B_ROWS, QT>>>(x4);                 // ~48us, hides the chain

    cudaStreamWaitEvent(0, ev_join, 0);
    dim3 ggrid(NSLICE, ROWBLK);
    k_gemv<<<ggrid, GT, GEMV_SMEM>>>(x4);
    k_finish<<<B_ROWS / 128, 128>>>(b, out);
}